// round 11
// baseline (speedup 1.0000x reference)
#include <cuda_runtime.h>
#include <cuda_fp16.h>
#include <cstdint>
#include <math.h>

// Problem dims (fixed)
#define B_   2
#define L_   2048
#define D_   512
#define NH_  8
#define HD_  64
#define NL_  4
#define DM_  2048
#define V_   32000
#define BL_  (B_ * L_)     // 4096
#define D3_  (3 * D_)      // 1536

// ---------------- scratch (device globals; no allocations allowed) ----------
__device__ float g_h[(size_t)BL_ * D_];            // residual stream
__device__ __align__(16) __half g_q16[(size_t)BL_ * D3_];   // fused qkv fp16
__device__ __align__(16) __half g_xh[(size_t)BL_ * DM_], g_xl[(size_t)BL_ * DM_];
__device__ __align__(16) __half g_yh[(size_t)BL_ * DM_], g_yl[(size_t)BL_ * DM_];

// fp16 weights [N,K] layout (transposed), hi only (2-pass split uses act lo)
__device__ __align__(16) __half g_wq_h[(size_t)NL_ * D3_ * D_];
__device__ __align__(16) __half g_wo_h[(size_t)NL_ * D_ * D_];
__device__ __align__(16) __half g_w1_h[(size_t)NL_ * DM_ * D_];
__device__ __align__(16) __half g_w2_h[(size_t)NL_ * D_ * DM_];
__device__ __align__(16) __half g_hd_h[(size_t)V_ * D_];

// ======================= PTX helpers (sm_80-level only) ======================
__device__ __forceinline__ uint32_t smem_u32(const void* p) {
    uint32_t a;
    asm("{ .reg .u64 t; cvta.to.shared.u64 t, %1; cvt.u32.u64 %0, t; }" : "=r"(a) : "l"(p));
    return a;
}
__device__ __forceinline__ void cpasync16(uint32_t dst, const void* src) {
    asm volatile("cp.async.cg.shared.global [%0], [%1], 16;" :: "r"(dst), "l"(src));
}
#define CP_COMMIT() asm volatile("cp.async.commit_group;" ::: "memory")
#define CP_WAIT(n)  asm volatile("cp.async.wait_group %0;" :: "n"(n) : "memory")

__device__ __forceinline__ void ldm4(uint32_t* r, uint32_t addr) {
    asm volatile("ldmatrix.sync.aligned.m8n8.x4.shared.b16 {%0,%1,%2,%3}, [%4];"
                 : "=r"(r[0]), "=r"(r[1]), "=r"(r[2]), "=r"(r[3]) : "r"(addr));
}
__device__ __forceinline__ void ldm4t(uint32_t* r, uint32_t addr) {
    asm volatile("ldmatrix.sync.aligned.m8n8.x4.trans.shared.b16 {%0,%1,%2,%3}, [%4];"
                 : "=r"(r[0]), "=r"(r[1]), "=r"(r[2]), "=r"(r[3]) : "r"(addr));
}
__device__ __forceinline__ void mma16816(float* c, const uint32_t* a, const uint32_t* b) {
    asm volatile("mma.sync.aligned.m16n8k16.row.col.f32.f16.f16.f32 "
                 "{%0,%1,%2,%3}, {%4,%5,%6,%7}, {%8,%9}, {%0,%1,%2,%3};"
                 : "+f"(c[0]), "+f"(c[1]), "+f"(c[2]), "+f"(c[3])
                 : "r"(a[0]), "r"(a[1]), "r"(a[2]), "r"(a[3]), "r"(b[0]), "r"(b[1]));
}
__device__ __forceinline__ uint32_t pack_h2(float a, float b) {
    __half2 h = __floats2half2_rn(a, b);
    return *(uint32_t*)&h;
}

// ======================= weight transpose (batched, hi only) =================
// W [K,N] fp32 row-major (per layer, stride win) -> Wh [N,K] fp16 (stride wout)
__global__ __launch_bounds__(256) void wsplit_kernel(const float* __restrict__ W,
                                                     int K, int N,
                                                     __half* __restrict__ Wh,
                                                     size_t win, size_t wout) {
    const float* Wp = W + blockIdx.z * win;
    __half* Whp = Wh + blockIdx.z * wout;
    __shared__ float t[32][33];
    int nt = blockIdx.x * 32, kt = blockIdx.y * 32;
    int tx = threadIdx.x & 31, ty = threadIdx.x >> 5;
#pragma unroll
    for (int i = 0; i < 32; i += 8)
        t[ty + i][tx] = Wp[(size_t)(kt + ty + i) * N + nt + tx];
    __syncthreads();
#pragma unroll
    for (int i = 0; i < 32; i += 8) {
        int n = nt + ty + i, k = kt + tx;
        Whp[(size_t)n * K + k] = __float2half(t[tx][ty + i]);
    }
}

// ======================= HMMA split GEMM (3-stage pipeline) ==================
// C = A[M,K] @ B^T (B stored [N,K]); npass: 1 = Ah*Bh; 2 = Ah*Bh + Al*Bh.
// out mode: 0 = fp32 C (+resid); 1 = fp16 H; 2 = fp16 split H,Hl. act=1 -> GELU.
#define TILE_B   (128 * 40 * 2)
#define STAGE_B  (3 * TILE_B)              // Ah, Al, Bh
#define NSTAGE   3
#define GSMEM    (NSTAGE * STAGE_B)        // 92160 bytes

__global__ __launch_bounds__(256) void gemm_hmma_kernel(
    int M, int N, int K,
    const __half* __restrict__ Ah, const __half* __restrict__ Al,
    const __half* __restrict__ Bh,
    const float* __restrict__ bias, const float* __restrict__ resid,
    float* __restrict__ C, __half* __restrict__ H, __half* __restrict__ Hl,
    int act, int npass, int mode) {
    extern __shared__ char smem[];
    uint32_t sbase = smem_u32(smem);
    int tid = threadIdx.x, lane = tid & 31, wid = tid >> 5;
    int wm = wid & 1, wn = wid >> 1;
    int mblk = blockIdx.y * 128, nblk = blockIdx.x * 128;

    const __half* pAh = Ah + (size_t)mblk * K;
    const __half* pAl = Al + (size_t)mblk * K;
    const __half* pBh = Bh + (size_t)nblk * K;

    int lrow = tid >> 2;
    int lseg = tid & 3;
    uint32_t so0 = (uint32_t)(lrow * 80 + lseg * 16);
    uint32_t so1 = (uint32_t)((lrow + 64) * 80 + lseg * 16);

    int nchunks = K >> 5;

#define LOAD_STAGE(kc, stg) do {                                               \
        uint32_t sb_ = sbase + (stg) * STAGE_B;                                \
        size_t go_ = (size_t)(kc) * 32 + lseg * 8;                             \
        cpasync16(sb_ + 0 * TILE_B + so0, pAh + (size_t)lrow * K + go_);       \
        cpasync16(sb_ + 2 * TILE_B + so0, pBh + (size_t)lrow * K + go_);       \
        cpasync16(sb_ + 0 * TILE_B + so1, pAh + (size_t)(lrow + 64) * K + go_);\
        cpasync16(sb_ + 2 * TILE_B + so1, pBh + (size_t)(lrow + 64) * K + go_);\
        if (npass >= 2) {                                                      \
            cpasync16(sb_ + 1 * TILE_B + so0, pAl + (size_t)lrow * K + go_);   \
            cpasync16(sb_ + 1 * TILE_B + so1, pAl + (size_t)(lrow + 64) * K + go_);\
        }                                                                      \
        CP_COMMIT();                                                           \
    } while (0)

    float acc[4][4][4];
#pragma unroll
    for (int i = 0; i < 4; i++)
#pragma unroll
        for (int j = 0; j < 4; j++)
#pragma unroll
            for (int u = 0; u < 4; u++) acc[i][j][u] = 0.0f;

    int arow = lane & 15;
    int akof = (lane & 16) ? 8 : 0;
    int brow = (lane & 7) + ((lane & 16) ? 8 : 0);
    int bkof = (lane & 8) ? 8 : 0;

    LOAD_STAGE(0, 0);
    if (nchunks > 1) LOAD_STAGE(1, 1);

    for (int kc = 0; kc < nchunks; kc++) {
        // wait for stage kc to land (allow the one group issued after it)
        if (kc + 1 < nchunks) CP_WAIT(1); else CP_WAIT(0);
        __syncthreads();   // data visible; all warps done reading stage (kc+2)%3
        if (kc + 2 < nchunks) LOAD_STAGE(kc + 2, (kc + 2) % NSTAGE);

        uint32_t sb = sbase + (kc % NSTAGE) * STAGE_B;
#pragma unroll
        for (int ks = 0; ks < 2; ks++) {
            int k16 = ks * 16;
            uint32_t ah[4][4], al[4][4], bh[4][4];
#pragma unroll
            for (int mt = 0; mt < 4; mt++) {
                uint32_t off = (uint32_t)((wm * 64 + mt * 16 + arow) * 40 + k16 + akof) * 2;
                ldm4(ah[mt], sb + 0 * TILE_B + off);
                if (npass >= 2) ldm4(al[mt], sb + 1 * TILE_B + off);
            }
#pragma unroll
            for (int pr = 0; pr < 2; pr++) {
                uint32_t off = (uint32_t)((wn * 32 + pr * 16 + brow) * 40 + k16 + bkof) * 2;
                ldm4(bh[pr * 2], sb + 2 * TILE_B + off);
            }
#pragma unroll
            for (int mt = 0; mt < 4; mt++) {
#pragma unroll
                for (int nt = 0; nt < 4; nt++) {
                    const uint32_t* bhf = &bh[(nt >> 1) * 2][(nt & 1) * 2];
                    mma16816(acc[mt][nt], ah[mt], bhf);
                    if (npass >= 2) mma16816(acc[mt][nt], al[mt], bhf);
                }
            }
        }
    }

    int r = lane >> 2, c2 = (lane & 3) * 2;
#pragma unroll
    for (int mt = 0; mt < 4; mt++) {
#pragma unroll
        for (int nt = 0; nt < 4; nt++) {
            int n0 = nblk + wn * 32 + nt * 8 + c2;
            float b0 = 0.f, b1 = 0.f;
            if (bias) { b0 = bias[n0]; b1 = bias[n0 + 1]; }
#pragma unroll
            for (int hr = 0; hr < 2; hr++) {
                int m = mblk + wm * 64 + mt * 16 + r + hr * 8;
                float v0 = acc[mt][nt][hr * 2 + 0] + b0;
                float v1 = acc[mt][nt][hr * 2 + 1] + b1;
                if (act == 1) {
                    v0 = 0.5f * v0 * (1.0f + erff(v0 * 0.70710678118654752f));
                    v1 = 0.5f * v1 * (1.0f + erff(v1 * 0.70710678118654752f));
                }
                if (mode == 0) {
                    if (resid) {
                        const float* rp = resid + (size_t)m * N + n0;
                        v0 += rp[0]; v1 += rp[1];
                    }
                    *(float2*)(C + (size_t)m * N + n0) = make_float2(v0, v1);
                } else if (mode == 1) {
                    *(__half2*)(H + (size_t)m * N + n0) = __floats2half2_rn(v0, v1);
                } else {
                    __half h0 = __float2half(v0), h1 = __float2half(v1);
                    *(__half2*)(H + (size_t)m * N + n0) = __halves2half2(h0, h1);
                    *(__half2*)(Hl + (size_t)m * N + n0) =
                        __halves2half2(__float2half(v0 - __half2float(h0)),
                                       __float2half(v1 - __half2float(h1)));
                }
            }
        }
    }
}

// ======================= fused fp16 flash attention ==========================
// Per CTA: one (bh, q-tile of 128). 8 warps x 16 q-rows. K/V tiles of 64,
// double-buffered. Online softmax fp32; P fp16; O accum fp32; split output.
#define ASTR 72
#define SQ_H 0
#define SK_H (128 * ASTR)
#define SV_H (128 * ASTR + 2 * 64 * ASTR)
#define ATT_SMEM ((128 * ASTR + 4 * 64 * ASTR) * 2)

__global__ __launch_bounds__(256) void attn_kernel(const __half* __restrict__ qkv,
                                                   __half* __restrict__ oh,
                                                   __half* __restrict__ ol) {
    int bh = blockIdx.y, b = bh >> 3, h = bh & 7;
    int qb = gridDim.x - 1 - blockIdx.x;       // heavy tiles first
    extern __shared__ char smc[];
    uint32_t sbase = smem_u32(smc);
    int tid = threadIdx.x, lane = tid & 31, wid = tid >> 5;

    const __half* qg = qkv + (size_t)(b * L_ + qb * 128) * D3_ + h * 64;
#pragma unroll
    for (int i = 0; i < 4; i++) {
        int idx = tid + i * 256;
        int row = idx >> 3, seg = idx & 7;
        cpasync16(sbase + (uint32_t)(SQ_H + row * ASTR + seg * 8) * 2,
                  qg + (size_t)row * D3_ + seg * 8);
    }
    CP_COMMIT();

#define LOAD_KV(kt, stg) do {                                                       \
        const __half* kg_ = qkv + (size_t)(b * L_ + (kt) * 64) * D3_ + D_ + h * 64; \
        const __half* vg_ = kg_ + D_;                                               \
        _Pragma("unroll")                                                           \
        for (int i_ = 0; i_ < 2; i_++) {                                            \
            int idx_ = tid + i_ * 256;                                              \
            int row_ = idx_ >> 3, seg_ = idx_ & 7;                                  \
            cpasync16(sbase + (uint32_t)(SK_H + (stg) * 64 * ASTR + row_ * ASTR + seg_ * 8) * 2, \
                      kg_ + (size_t)row_ * D3_ + seg_ * 8);                         \
            cpasync16(sbase + (uint32_t)(SV_H + (stg) * 64 * ASTR + row_ * ASTR + seg_ * 8) * 2, \
                      vg_ + (size_t)row_ * D3_ + seg_ * 8);                         \
        }                                                                           \
        CP_COMMIT();                                                                \
    } while (0)

    int nkt = 2 * qb + 2;
    LOAD_KV(0, 0);
    CP_WAIT(0);
    __syncthreads();

    uint32_t qf[4][4];
    int arow = lane & 15, akof = (lane & 16) ? 8 : 0;
#pragma unroll
    for (int t = 0; t < 4; t++)
        ldm4(qf[t], sbase + (uint32_t)(SQ_H + (wid * 16 + arow) * ASTR + t * 16 + akof) * 2);

    float mrow0 = -INFINITY, mrow1 = -INFINITY, lrow0 = 0.f, lrow1 = 0.f;
    float o[8][4];
#pragma unroll
    for (int n = 0; n < 8; n++)
#pragma unroll
        for (int u = 0; u < 4; u++) o[n][u] = 0.f;

    int r0 = qb * 128 + wid * 16 + (lane >> 2);
    int lg = lane >> 3, lr = lane & 7;

    for (int kt = 0; kt < nkt; kt++) {
        if (kt + 1 < nkt) { LOAD_KV(kt + 1, (kt + 1) & 1); CP_WAIT(1); }
        else { CP_WAIT(0); }
        __syncthreads();
        bool active = (kt * 64 <= qb * 128 + wid * 16 + 15);
        if (active) {
            uint32_t skb = sbase + (uint32_t)(SK_H + (kt & 1) * 64 * ASTR) * 2;
            uint32_t svb = sbase + (uint32_t)(SV_H + (kt & 1) * 64 * ASTR) * 2;
            float s[8][4];
#pragma unroll
            for (int n = 0; n < 8; n++)
#pragma unroll
                for (int u = 0; u < 4; u++) s[n][u] = 0.f;
#pragma unroll
            for (int t = 0; t < 4; t++) {
#pragma unroll
                for (int g = 0; g < 4; g++) {
                    uint32_t kb[4];
                    int row = g * 16 + lr + ((lg >= 2) ? 8 : 0);
                    int col = t * 16 + ((lg & 1) ? 8 : 0);
                    ldm4(kb, skb + (uint32_t)(row * ASTR + col) * 2);
                    mma16816(s[2 * g], qf[t], kb);
                    mma16816(s[2 * g + 1], qf[t], kb + 2);
                }
            }
            const float sc = 0.125f;
#pragma unroll
            for (int n = 0; n < 8; n++)
#pragma unroll
                for (int u = 0; u < 4; u++) s[n][u] *= sc;
            if (kt * 64 + 63 > r0) {
                int cbase = kt * 64 + 2 * (lane & 3);
#pragma unroll
                for (int n = 0; n < 8; n++) {
                    int c0 = cbase + n * 8;
                    if (c0 > r0)         s[n][0] = -INFINITY;
                    if (c0 + 1 > r0)     s[n][1] = -INFINITY;
                    if (c0 > r0 + 8)     s[n][2] = -INFINITY;
                    if (c0 + 1 > r0 + 8) s[n][3] = -INFINITY;
                }
            }
            float mx0 = -INFINITY, mx1 = -INFINITY;
#pragma unroll
            for (int n = 0; n < 8; n++) {
                mx0 = fmaxf(mx0, fmaxf(s[n][0], s[n][1]));
                mx1 = fmaxf(mx1, fmaxf(s[n][2], s[n][3]));
            }
            mx0 = fmaxf(mx0, __shfl_xor_sync(0xFFFFFFFFu, mx0, 1));
            mx0 = fmaxf(mx0, __shfl_xor_sync(0xFFFFFFFFu, mx0, 2));
            mx1 = fmaxf(mx1, __shfl_xor_sync(0xFFFFFFFFu, mx1, 1));
            mx1 = fmaxf(mx1, __shfl_xor_sync(0xFFFFFFFFu, mx1, 2));
            float mn0 = fmaxf(mrow0, mx0), mn1 = fmaxf(mrow1, mx1);
            float al0 = __expf(mrow0 - mn0), al1 = __expf(mrow1 - mn1);
            mrow0 = mn0; mrow1 = mn1;
            float sum0 = 0.f, sum1 = 0.f;
#pragma unroll
            for (int n = 0; n < 8; n++) {
                s[n][0] = __expf(s[n][0] - mn0);
                s[n][1] = __expf(s[n][1] - mn0);
                s[n][2] = __expf(s[n][2] - mn1);
                s[n][3] = __expf(s[n][3] - mn1);
                sum0 += s[n][0] + s[n][1];
                sum1 += s[n][2] + s[n][3];
            }
            sum0 += __shfl_xor_sync(0xFFFFFFFFu, sum0, 1);
            sum0 += __shfl_xor_sync(0xFFFFFFFFu, sum0, 2);
            sum1 += __shfl_xor_sync(0xFFFFFFFFu, sum1, 1);
            sum1 += __shfl_xor_sync(0xFFFFFFFFu, sum1, 2);
            lrow0 = lrow0 * al0 + sum0;
            lrow1 = lrow1 * al1 + sum1;
#pragma unroll
            for (int n = 0; n < 8; n++) {
                o[n][0] *= al0; o[n][1] *= al0;
                o[n][2] *= al1; o[n][3] *= al1;
            }
            uint32_t pf[4][4];
#pragma unroll
            for (int t = 0; t < 4; t++) {
                pf[t][0] = pack_h2(s[2 * t][0], s[2 * t][1]);
                pf[t][1] = pack_h2(s[2 * t][2], s[2 * t][3]);
                pf[t][2] = pack_h2(s[2 * t + 1][0], s[2 * t + 1][1]);
                pf[t][3] = pack_h2(s[2 * t + 1][2], s[2 * t + 1][3]);
            }
#pragma unroll
            for (int t = 0; t < 4; t++) {
#pragma unroll
                for (int g = 0; g < 4; g++) {
                    uint32_t vb[4];
                    int row = t * 16 + lr + ((lg & 1) ? 8 : 0);
                    int col = g * 16 + ((lg >= 2) ? 8 : 0);
                    ldm4t(vb, svb + (uint32_t)(row * ASTR + col) * 2);
                    mma16816(o[2 * g], pf[t], vb);
                    mma16816(o[2 * g + 1], pf[t], vb + 2);
                }
            }
        }
        __syncthreads();
    }

    float inv0 = 1.f / lrow0, inv1 = 1.f / lrow1;
    size_t gr0 = (size_t)(b * L_ + r0);
    size_t gr1 = gr0 + 8;
    int col = h * 64 + 2 * (lane & 3);
#pragma unroll
    for (int n = 0; n < 8; n++) {
        int c = col + n * 8;
        float v0 = o[n][0] * inv0, v1 = o[n][1] * inv0;
        float v2 = o[n][2] * inv1, v3 = o[n][3] * inv1;
        __half h0 = __float2half(v0), h1 = __float2half(v1);
        __half h2 = __float2half(v2), h3 = __float2half(v3);
        *(__half2*)(oh + gr0 * D_ + c) = __halves2half2(h0, h1);
        *(__half2*)(ol + gr0 * D_ + c) =
            __halves2half2(__float2half(v0 - __half2float(h0)),
                           __float2half(v1 - __half2float(h1)));
        *(__half2*)(oh + gr1 * D_ + c) = __halves2half2(h2, h3);
        *(__half2*)(ol + gr1 * D_ + c) =
            __halves2half2(__float2half(v2 - __half2float(h2)),
                           __float2half(v3 - __half2float(h3)));
    }
}

// ======================= embedding / layernorm(+split) =======================
__global__ void embed_kernel(const int* __restrict__ x,
                             const float* __restrict__ tok,
                             const float* __restrict__ pos) {
    int i = blockIdx.x;
    int l = i & (L_ - 1);
    int idx = x[i];
    const float4* ts = (const float4*)(tok + (size_t)idx * D_);
    const float4* ps = (const float4*)(pos + (size_t)l * D_);
    float4* hp = (float4*)(g_h + (size_t)i * D_);
    for (int d = threadIdx.x; d < D_ / 4; d += blockDim.x) {
        float4 a = ts[d], b = ps[d];
        hp[d] = make_float4(a.x + b.x, a.y + b.y, a.z + b.z, a.w + b.w);
    }
}

__global__ __launch_bounds__(256) void ln_split_kernel(const float* __restrict__ x,
                                                       const float* __restrict__ g,
                                                       const float* __restrict__ bta,
                                                       __half* __restrict__ xh,
                                                       __half* __restrict__ xl) {
    int row = blockIdx.x, t = threadIdx.x;
    float2 v = ((const float2*)(x + (size_t)row * D_))[t];
    __shared__ float rs[256], rq[256];
    rs[t] = v.x + v.y;
    rq[t] = v.x * v.x + v.y * v.y;
    __syncthreads();
    for (int s = 128; s; s >>= 1) {
        if (t < s) { rs[t] += rs[t + s]; rq[t] += rq[t + s]; }
        __syncthreads();
    }
    float mu  = rs[0] * (1.0f / D_);
    float var = rq[0] * (1.0f / D_) - mu * mu;
    float inv = rsqrtf(var + 1e-5f);
    float2 gv = ((const float2*)g)[t];
    float2 bv = ((const float2*)bta)[t];
    float o0 = (v.x - mu) * inv * gv.x + bv.x;
    float o1 = (v.y - mu) * inv * gv.y + bv.y;
    __half h0 = __float2half(o0), h1 = __float2half(o1);
    ((__half2*)(xh + (size_t)row * D_))[t] = __halves2half2(h0, h1);
    ((__half2*)(xl + (size_t)row * D_))[t] =
        __halves2half2(__float2half(o0 - __half2float(h0)),
                       __float2half(o1 - __half2float(h1)));
}

// ======================= host orchestration ==================================
static inline void gemm_tc(int M, int N, int K,
                           const __half* ah, const __half* al,
                           const __half* bh,
                           const float* bias, const float* resid, float* C,
                           __half* H, __half* Hl, int act, int npass, int mode) {
    gemm_hmma_kernel<<<dim3(N / 128, M / 128), 256, GSMEM>>>(
        M, N, K, ah, al, bh, bias, resid, C, H, Hl, act, npass, mode);
}

extern "C" void kernel_launch(void* const* d_in, const int* in_sizes, int n_in,
                              void* d_out, int out_size) {
    const int*   x     = (const int*)d_in[0];
    const float* tok   = (const float*)d_in[1];
    const float* pos   = (const float*)d_in[2];
    const float* ln1g  = (const float*)d_in[3];
    const float* ln1b  = (const float*)d_in[4];
    const float* qkvw  = (const float*)d_in[5];
    const float* qkvb  = (const float*)d_in[6];
    const float* outw  = (const float*)d_in[7];
    const float* outb  = (const float*)d_in[8];
    const float* ln2g  = (const float*)d_in[9];
    const float* ln2b  = (const float*)d_in[10];
    const float* w1    = (const float*)d_in[11];
    const float* b1    = (const float*)d_in[12];
    const float* w2    = (const float*)d_in[13];
    const float* b2    = (const float*)d_in[14];
    const float* lnfg  = (const float*)d_in[15];
    const float* lnfb  = (const float*)d_in[16];
    const float* headw = (const float*)d_in[17];
    float* out = (float*)d_out;

    cudaFuncSetAttribute(gemm_hmma_kernel,
                         cudaFuncAttributeMaxDynamicSharedMemorySize, GSMEM);
    cudaFuncSetAttribute(attn_kernel,
                         cudaFuncAttributeMaxDynamicSharedMemorySize, ATT_SMEM);

    float* ph;
    cudaGetSymbolAddress((void**)&ph, g_h);
    __half *wqh, *woh, *w1h, *w2h, *hdh;
    __half *q16, *xh, *xl, *yh, *yl;
    cudaGetSymbolAddress((void**)&wqh, g_wq_h);
    cudaGetSymbolAddress((void**)&woh, g_wo_h);
    cudaGetSymbolAddress((void**)&w1h, g_w1_h);
    cudaGetSymbolAddress((void**)&w2h, g_w2_h);
    cudaGetSymbolAddress((void**)&hdh, g_hd_h);
    cudaGetSymbolAddress((void**)&q16, g_q16);
    cudaGetSymbolAddress((void**)&xh, g_xh);    cudaGetSymbolAddress((void**)&xl, g_xl);
    cudaGetSymbolAddress((void**)&yh, g_yh);    cudaGetSymbolAddress((void**)&yl, g_yl);

    // batched weight transposes: one launch per weight type (z = layer)
    wsplit_kernel<<<dim3(D3_ / 32, D_ / 32, NL_), 256>>>(
        qkvw, D_, D3_, wqh, (size_t)D_ * D3_, (size_t)D3_ * D_);
    wsplit_kernel<<<dim3(D_ / 32, D_ / 32, NL_), 256>>>(
        outw, D_, D_, woh, (size_t)D_ * D_, (size_t)D_ * D_);
    wsplit_kernel<<<dim3(DM_ / 32, D_ / 32, NL_), 256>>>(
        w1, D_, DM_, w1h, (size_t)D_ * DM_, (size_t)DM_ * D_);
    wsplit_kernel<<<dim3(D_ / 32, DM_ / 32, NL_), 256>>>(
        w2, DM_, D_, w2h, (size_t)DM_ * D_, (size_t)D_ * DM_);
    wsplit_kernel<<<dim3(V_ / 32, D_ / 32, 1), 256>>>(
        headw, D_, V_, hdh, 0, 0);

    embed_kernel<<<BL_, 128>>>(x, tok, pos);

    for (int i = 0; i < NL_; i++) {
        ln_split_kernel<<<BL_, 256>>>(ph, ln1g + i * D_, ln1b + i * D_, xh, xl);
        // QKV -> fp16 (mode 1), 2-pass
        gemm_tc(BL_, D3_, D_, xh, xl,
                wqh + (size_t)i * D3_ * D_,
                qkvb + (size_t)i * D3_, nullptr, nullptr, q16, nullptr, 0, 2, 1);
        // fused flash attention -> split O (proj input)
        attn_kernel<<<dim3(L_ / 128, B_ * NH_), 256, ATT_SMEM>>>(q16, xh, xl);
        // proj + residual (mode 0), 2-pass
        gemm_tc(BL_, D_, D_, xh, xl,
                woh + (size_t)i * D_ * D_,
                outb + (size_t)i * D_, ph, ph, nullptr, nullptr, 0, 2, 0);
        ln_split_kernel<<<BL_, 256>>>(ph, ln2g + i * D_, ln2b + i * D_, xh, xl);
        // MLP up + GELU -> split (mode 2), 2-pass
        gemm_tc(BL_, DM_, D_, xh, xl,
                w1h + (size_t)i * DM_ * D_,
                b1 + (size_t)i * DM_, nullptr, nullptr, yh, yl, 1, 2, 2);
        // MLP down + residual (mode 0), 2-pass
        gemm_tc(BL_, D_, DM_, yh, yl,
                w2h + (size_t)i * D_ * DM_,
                b2 + (size_t)i * D_, ph, ph, nullptr, nullptr, 0, 2, 0);
    }

    ln_split_kernel<<<BL_, 256>>>(ph, lnfg, lnfb, xh, xl);
    // vocab head: 1-pass (Ah*Bh)
    gemm_tc(BL_, V_, D_, xh, xl, hdh, nullptr, nullptr, out,
            nullptr, nullptr, 0, 1, 0);
}

// round 15
// speedup vs baseline: 1.0715x; 1.0715x over previous
#include <cuda_runtime.h>
#include <cuda_fp16.h>
#include <cstdint>
#include <math.h>

// Problem dims (fixed)
#define B_   2
#define L_   2048
#define D_   512
#define NH_  8
#define HD_  64
#define NL_  4
#define DM_  2048
#define V_   32000
#define BL_  (B_ * L_)     // 4096
#define D3_  (3 * D_)      // 1536

// ---------------- scratch (device globals; no allocations allowed) ----------
__device__ float g_h[(size_t)BL_ * D_];            // residual stream
__device__ __align__(16) __half g_q16[(size_t)BL_ * D3_];   // fused qkv fp16
__device__ __align__(16) __half g_xh[(size_t)BL_ * DM_], g_xl[(size_t)BL_ * DM_];
__device__ __align__(16) __half g_yh[(size_t)BL_ * DM_], g_yl[(size_t)BL_ * DM_];

// fp16 weights [N,K] layout (transposed), hi only
__device__ __align__(16) __half g_wq_h[(size_t)NL_ * D3_ * D_];
__device__ __align__(16) __half g_wo_h[(size_t)NL_ * D_ * D_];
__device__ __align__(16) __half g_w1_h[(size_t)NL_ * DM_ * D_];
__device__ __align__(16) __half g_w2_h[(size_t)NL_ * D_ * DM_];
__device__ __align__(16) __half g_hd_h[(size_t)V_ * D_];

// ======================= PTX helpers (sm_80-level only) ======================
__device__ __forceinline__ uint32_t smem_u32(const void* p) {
    uint32_t a;
    asm("{ .reg .u64 t; cvta.to.shared.u64 t, %1; cvt.u32.u64 %0, t; }" : "=r"(a) : "l"(p));
    return a;
}
__device__ __forceinline__ void cpasync16(uint32_t dst, const void* src) {
    asm volatile("cp.async.cg.shared.global [%0], [%1], 16;" :: "r"(dst), "l"(src));
}
#define CP_COMMIT() asm volatile("cp.async.commit_group;" ::: "memory")
#define CP_WAIT(n)  asm volatile("cp.async.wait_group %0;" :: "n"(n) : "memory")

__device__ __forceinline__ void ldm4(uint32_t* r, uint32_t addr) {
    asm volatile("ldmatrix.sync.aligned.m8n8.x4.shared.b16 {%0,%1,%2,%3}, [%4];"
                 : "=r"(r[0]), "=r"(r[1]), "=r"(r[2]), "=r"(r[3]) : "r"(addr));
}
__device__ __forceinline__ void ldm4t(uint32_t* r, uint32_t addr) {
    asm volatile("ldmatrix.sync.aligned.m8n8.x4.trans.shared.b16 {%0,%1,%2,%3}, [%4];"
                 : "=r"(r[0]), "=r"(r[1]), "=r"(r[2]), "=r"(r[3]) : "r"(addr));
}
__device__ __forceinline__ void mma16816(float* c, const uint32_t* a, const uint32_t* b) {
    asm volatile("mma.sync.aligned.m16n8k16.row.col.f32.f16.f16.f32 "
                 "{%0,%1,%2,%3}, {%4,%5,%6,%7}, {%8,%9}, {%0,%1,%2,%3};"
                 : "+f"(c[0]), "+f"(c[1]), "+f"(c[2]), "+f"(c[3])
                 : "r"(a[0]), "r"(a[1]), "r"(a[2]), "r"(a[3]), "r"(b[0]), "r"(b[1]));
}
// fp16 accumulation variant (d,c are 2x b32 = 4 halves; same thread mapping)
__device__ __forceinline__ void mma16816h(uint32_t* c, const uint32_t* a, const uint32_t* b) {
    asm volatile("mma.sync.aligned.m16n8k16.row.col.f16.f16.f16.f16 "
                 "{%0,%1}, {%2,%3,%4,%5}, {%6,%7}, {%0,%1};"
                 : "+r"(c[0]), "+r"(c[1])
                 : "r"(a[0]), "r"(a[1]), "r"(a[2]), "r"(a[3]), "r"(b[0]), "r"(b[1]));
}
__device__ __forceinline__ uint32_t pack_h2(float a, float b) {
    __half2 h = __floats2half2_rn(a, b);
    return *(uint32_t*)&h;
}

// ======================= weight transpose (batched, hi only) =================
__global__ __launch_bounds__(256) void wsplit_kernel(const float* __restrict__ W,
                                                     int K, int N,
                                                     __half* __restrict__ Wh,
                                                     size_t win, size_t wout) {
    const float* Wp = W + blockIdx.z * win;
    __half* Whp = Wh + blockIdx.z * wout;
    __shared__ float t[32][33];
    int nt = blockIdx.x * 32, kt = blockIdx.y * 32;
    int tx = threadIdx.x & 31, ty = threadIdx.x >> 5;
#pragma unroll
    for (int i = 0; i < 32; i += 8)
        t[ty + i][tx] = Wp[(size_t)(kt + ty + i) * N + nt + tx];
    __syncthreads();
#pragma unroll
    for (int i = 0; i < 32; i += 8) {
        int n = nt + ty + i, k = kt + tx;
        Whp[(size_t)n * K + k] = __float2half(t[tx][ty + i]);
    }
}

// ======================= HMMA split GEMM (2-stage, fp32 acc) =================
#define TILE_B   (128 * 40 * 2)
#define STAGE_B  (3 * TILE_B)              // Ah, Al, Bh
#define GSMEM    (2 * STAGE_B)

__global__ __launch_bounds__(256) void gemm_hmma_kernel(
    int M, int N, int K,
    const __half* __restrict__ Ah, const __half* __restrict__ Al,
    const __half* __restrict__ Bh,
    const float* __restrict__ bias, const float* __restrict__ resid,
    float* __restrict__ C, __half* __restrict__ H, __half* __restrict__ Hl,
    int act, int npass, int mode) {
    extern __shared__ char smem[];
    uint32_t sbase = smem_u32(smem);
    int tid = threadIdx.x, lane = tid & 31, wid = tid >> 5;
    int wm = wid & 1, wn = wid >> 1;
    int mblk = blockIdx.y * 128, nblk = blockIdx.x * 128;

    const __half* pAh = Ah + (size_t)mblk * K;
    const __half* pAl = Al + (size_t)mblk * K;
    const __half* pBh = Bh + (size_t)nblk * K;

    int lrow = tid >> 2;
    int lseg = tid & 3;
    uint32_t so0 = (uint32_t)(lrow * 80 + lseg * 16);
    uint32_t so1 = (uint32_t)((lrow + 64) * 80 + lseg * 16);

    int nchunks = K >> 5;

#define LOAD_STAGE(kc, stg) do {                                               \
        uint32_t sb_ = sbase + (stg) * STAGE_B;                                \
        size_t go_ = (size_t)(kc) * 32 + lseg * 8;                             \
        cpasync16(sb_ + 0 * TILE_B + so0, pAh + (size_t)lrow * K + go_);       \
        cpasync16(sb_ + 2 * TILE_B + so0, pBh + (size_t)lrow * K + go_);       \
        cpasync16(sb_ + 0 * TILE_B + so1, pAh + (size_t)(lrow + 64) * K + go_);\
        cpasync16(sb_ + 2 * TILE_B + so1, pBh + (size_t)(lrow + 64) * K + go_);\
        if (npass >= 2) {                                                      \
            cpasync16(sb_ + 1 * TILE_B + so0, pAl + (size_t)lrow * K + go_);   \
            cpasync16(sb_ + 1 * TILE_B + so1, pAl + (size_t)(lrow + 64) * K + go_);\
        }                                                                      \
        CP_COMMIT();                                                           \
    } while (0)

    float acc[4][4][4];
#pragma unroll
    for (int i = 0; i < 4; i++)
#pragma unroll
        for (int j = 0; j < 4; j++)
#pragma unroll
            for (int u = 0; u < 4; u++) acc[i][j][u] = 0.0f;

    int arow = lane & 15;
    int akof = (lane & 16) ? 8 : 0;
    int brow = (lane & 7) + ((lane & 16) ? 8 : 0);
    int bkof = (lane & 8) ? 8 : 0;

    LOAD_STAGE(0, 0);
    for (int kc = 0; kc < nchunks; kc++) {
        if (kc + 1 < nchunks) {
            LOAD_STAGE(kc + 1, (kc + 1) & 1);
            CP_WAIT(1);
        } else {
            CP_WAIT(0);
        }
        __syncthreads();
        uint32_t sb = sbase + (kc & 1) * STAGE_B;
#pragma unroll
        for (int ks = 0; ks < 2; ks++) {
            int k16 = ks * 16;
            uint32_t ah[4][4], al[4][4], bh[4][4];
#pragma unroll
            for (int mt = 0; mt < 4; mt++) {
                uint32_t off = (uint32_t)((wm * 64 + mt * 16 + arow) * 40 + k16 + akof) * 2;
                ldm4(ah[mt], sb + 0 * TILE_B + off);
                if (npass >= 2) ldm4(al[mt], sb + 1 * TILE_B + off);
            }
#pragma unroll
            for (int pr = 0; pr < 2; pr++) {
                uint32_t off = (uint32_t)((wn * 32 + pr * 16 + brow) * 40 + k16 + bkof) * 2;
                ldm4(bh[pr * 2], sb + 2 * TILE_B + off);
            }
#pragma unroll
            for (int mt = 0; mt < 4; mt++) {
#pragma unroll
                for (int nt = 0; nt < 4; nt++) {
                    const uint32_t* bhf = &bh[(nt >> 1) * 2][(nt & 1) * 2];
                    mma16816(acc[mt][nt], ah[mt], bhf);
                    if (npass >= 2) mma16816(acc[mt][nt], al[mt], bhf);
                }
            }
        }
        __syncthreads();
    }

    int r = lane >> 2, c2 = (lane & 3) * 2;
#pragma unroll
    for (int mt = 0; mt < 4; mt++) {
#pragma unroll
        for (int nt = 0; nt < 4; nt++) {
            int n0 = nblk + wn * 32 + nt * 8 + c2;
            float b0 = 0.f, b1 = 0.f;
            if (bias) { b0 = bias[n0]; b1 = bias[n0 + 1]; }
#pragma unroll
            for (int hr = 0; hr < 2; hr++) {
                int m = mblk + wm * 64 + mt * 16 + r + hr * 8;
                float v0 = acc[mt][nt][hr * 2 + 0] + b0;
                float v1 = acc[mt][nt][hr * 2 + 1] + b1;
                if (act == 1) {
                    v0 = 0.5f * v0 * (1.0f + erff(v0 * 0.70710678118654752f));
                    v1 = 0.5f * v1 * (1.0f + erff(v1 * 0.70710678118654752f));
                }
                if (mode == 0) {
                    if (resid) {
                        const float* rp = resid + (size_t)m * N + n0;
                        v0 += rp[0]; v1 += rp[1];
                    }
                    *(float2*)(C + (size_t)m * N + n0) = make_float2(v0, v1);
                } else if (mode == 1) {
                    *(__half2*)(H + (size_t)m * N + n0) = __floats2half2_rn(v0, v1);
                } else {
                    __half h0 = __float2half(v0), h1 = __float2half(v1);
                    *(__half2*)(H + (size_t)m * N + n0) = __halves2half2(h0, h1);
                    *(__half2*)(Hl + (size_t)m * N + n0) =
                        __halves2half2(__float2half(v0 - __half2float(h0)),
                                       __float2half(v1 - __half2float(h1)));
                }
            }
        }
    }
}

// ======================= head GEMM: fp16-acc with segment promotion ==========
// C[M,V] = Ah @ Bh^T, 1-pass, fp16 accumulators promoted to fp32 every 64 K.
#define HSTAGE_B (2 * TILE_B)              // Ah, Bh only
#define HSMEM    (2 * HSTAGE_B)            // 40960 bytes

__global__ __launch_bounds__(256) void gemm_head_kernel(
    int M, int N, int K,
    const __half* __restrict__ Ah, const __half* __restrict__ Bh,
    float* __restrict__ C) {
    extern __shared__ char smem[];
    uint32_t sbase = smem_u32(smem);
    int tid = threadIdx.x, lane = tid & 31, wid = tid >> 5;
    int wm = wid & 1, wn = wid >> 1;
    int mblk = blockIdx.y * 128, nblk = blockIdx.x * 128;

    const __half* pAh = Ah + (size_t)mblk * K;
    const __half* pBh = Bh + (size_t)nblk * K;

    int lrow = tid >> 2;
    int lseg = tid & 3;
    uint32_t so0 = (uint32_t)(lrow * 80 + lseg * 16);
    uint32_t so1 = (uint32_t)((lrow + 64) * 80 + lseg * 16);

    int nchunks = K >> 5;

#define HLOAD(kc, stg) do {                                                    \
        uint32_t sb_ = sbase + (stg) * HSTAGE_B;                               \
        size_t go_ = (size_t)(kc) * 32 + lseg * 8;                             \
        cpasync16(sb_ + 0 * TILE_B + so0, pAh + (size_t)lrow * K + go_);       \
        cpasync16(sb_ + 1 * TILE_B + so0, pBh + (size_t)lrow * K + go_);       \
        cpasync16(sb_ + 0 * TILE_B + so1, pAh + (size_t)(lrow + 64) * K + go_);\
        cpasync16(sb_ + 1 * TILE_B + so1, pBh + (size_t)(lrow + 64) * K + go_);\
        CP_COMMIT();                                                           \
    } while (0)

    float acc[4][4][4];
    uint32_t a16[4][4][2];
#pragma unroll
    for (int i = 0; i < 4; i++)
#pragma unroll
        for (int j = 0; j < 4; j++) {
#pragma unroll
            for (int u = 0; u < 4; u++) acc[i][j][u] = 0.0f;
            a16[i][j][0] = a16[i][j][1] = 0u;
        }

    int arow = lane & 15;
    int akof = (lane & 16) ? 8 : 0;
    int brow = (lane & 7) + ((lane & 16) ? 8 : 0);
    int bkof = (lane & 8) ? 8 : 0;

    HLOAD(0, 0);
    for (int kc = 0; kc < nchunks; kc++) {
        if (kc + 1 < nchunks) {
            HLOAD(kc + 1, (kc + 1) & 1);
            CP_WAIT(1);
        } else {
            CP_WAIT(0);
        }
        __syncthreads();
        uint32_t sb = sbase + (kc & 1) * HSTAGE_B;
#pragma unroll
        for (int ks = 0; ks < 2; ks++) {
            int k16 = ks * 16;
            uint32_t ah[4][4], bh[4][4];
#pragma unroll
            for (int mt = 0; mt < 4; mt++) {
                uint32_t off = (uint32_t)((wm * 64 + mt * 16 + arow) * 40 + k16 + akof) * 2;
                ldm4(ah[mt], sb + 0 * TILE_B + off);
            }
#pragma unroll
            for (int pr = 0; pr < 2; pr++) {
                uint32_t off = (uint32_t)((wn * 32 + pr * 16 + brow) * 40 + k16 + bkof) * 2;
                ldm4(bh[pr * 2], sb + 1 * TILE_B + off);
            }
#pragma unroll
            for (int mt = 0; mt < 4; mt++) {
#pragma unroll
                for (int nt = 0; nt < 4; nt++) {
                    const uint32_t* bhf = &bh[(nt >> 1) * 2][(nt & 1) * 2];
                    mma16816h(a16[mt][nt], ah[mt], bhf);
                }
            }
        }
        __syncthreads();
        // promote fp16 segment accumulators to fp32 every 2 chunks (64 K)
        if ((kc & 1) || kc + 1 == nchunks) {
#pragma unroll
            for (int mt = 0; mt < 4; mt++)
#pragma unroll
                for (int nt = 0; nt < 4; nt++) {
                    float2 f0 = __half22float2(*(__half2*)&a16[mt][nt][0]);
                    float2 f1 = __half22float2(*(__half2*)&a16[mt][nt][1]);
                    acc[mt][nt][0] += f0.x; acc[mt][nt][1] += f0.y;
                    acc[mt][nt][2] += f1.x; acc[mt][nt][3] += f1.y;
                    a16[mt][nt][0] = a16[mt][nt][1] = 0u;
                }
        }
    }

    int r = lane >> 2, c2 = (lane & 3) * 2;
#pragma unroll
    for (int mt = 0; mt < 4; mt++) {
#pragma unroll
        for (int nt = 0; nt < 4; nt++) {
            int n0 = nblk + wn * 32 + nt * 8 + c2;
#pragma unroll
            for (int hr = 0; hr < 2; hr++) {
                int m = mblk + wm * 64 + mt * 16 + r + hr * 8;
                *(float2*)(C + (size_t)m * N + n0) =
                    make_float2(acc[mt][nt][hr * 2 + 0], acc[mt][nt][hr * 2 + 1]);
            }
        }
    }
}

// ======================= fused fp16 flash attention ==========================
#define ASTR 72
#define SQ_H 0
#define SK_H (128 * ASTR)
#define SV_H (128 * ASTR + 2 * 64 * ASTR)
#define ATT_SMEM ((128 * ASTR + 4 * 64 * ASTR) * 2)

__global__ __launch_bounds__(256) void attn_kernel(const __half* __restrict__ qkv,
                                                   __half* __restrict__ oh,
                                                   __half* __restrict__ ol) {
    int bh = blockIdx.y, b = bh >> 3, h = bh & 7;
    int qb = gridDim.x - 1 - blockIdx.x;       // heavy tiles first
    extern __shared__ char smc[];
    uint32_t sbase = smem_u32(smc);
    int tid = threadIdx.x, lane = tid & 31, wid = tid >> 5;

    const __half* qg = qkv + (size_t)(b * L_ + qb * 128) * D3_ + h * 64;
#pragma unroll
    for (int i = 0; i < 4; i++) {
        int idx = tid + i * 256;
        int row = idx >> 3, seg = idx & 7;
        cpasync16(sbase + (uint32_t)(SQ_H + row * ASTR + seg * 8) * 2,
                  qg + (size_t)row * D3_ + seg * 8);
    }
    CP_COMMIT();

#define LOAD_KV(kt, stg) do {                                                       \
        const __half* kg_ = qkv + (size_t)(b * L_ + (kt) * 64) * D3_ + D_ + h * 64; \
        const __half* vg_ = kg_ + D_;                                               \
        _Pragma("unroll")                                                           \
        for (int i_ = 0; i_ < 2; i_++) {                                            \
            int idx_ = tid + i_ * 256;                                              \
            int row_ = idx_ >> 3, seg_ = idx_ & 7;                                  \
            cpasync16(sbase + (uint32_t)(SK_H + (stg) * 64 * ASTR + row_ * ASTR + seg_ * 8) * 2, \
                      kg_ + (size_t)row_ * D3_ + seg_ * 8);                         \
            cpasync16(sbase + (uint32_t)(SV_H + (stg) * 64 * ASTR + row_ * ASTR + seg_ * 8) * 2, \
                      vg_ + (size_t)row_ * D3_ + seg_ * 8);                         \
        }                                                                           \
        CP_COMMIT();                                                                \
    } while (0)

    int nkt = 2 * qb + 2;
    LOAD_KV(0, 0);
    CP_WAIT(0);
    __syncthreads();

    uint32_t qf[4][4];
    int arow = lane & 15, akof = (lane & 16) ? 8 : 0;
#pragma unroll
    for (int t = 0; t < 4; t++)
        ldm4(qf[t], sbase + (uint32_t)(SQ_H + (wid * 16 + arow) * ASTR + t * 16 + akof) * 2);

    float mrow0 = -INFINITY, mrow1 = -INFINITY, lrow0 = 0.f, lrow1 = 0.f;
    float o[8][4];
#pragma unroll
    for (int n = 0; n < 8; n++)
#pragma unroll
        for (int u = 0; u < 4; u++) o[n][u] = 0.f;

    int r0 = qb * 128 + wid * 16 + (lane >> 2);
    int lg = lane >> 3, lr = lane & 7;

    for (int kt = 0; kt < nkt; kt++) {
        if (kt + 1 < nkt) { LOAD_KV(kt + 1, (kt + 1) & 1); CP_WAIT(1); }
        else { CP_WAIT(0); }
        __syncthreads();
        bool active = (kt * 64 <= qb * 128 + wid * 16 + 15);
        if (active) {
            uint32_t skb = sbase + (uint32_t)(SK_H + (kt & 1) * 64 * ASTR) * 2;
            uint32_t svb = sbase + (uint32_t)(SV_H + (kt & 1) * 64 * ASTR) * 2;
            float s[8][4];
#pragma unroll
            for (int n = 0; n < 8; n++)
#pragma unroll
                for (int u = 0; u < 4; u++) s[n][u] = 0.f;
#pragma unroll
            for (int t = 0; t < 4; t++) {
#pragma unroll
                for (int g = 0; g < 4; g++) {
                    uint32_t kb[4];
                    int row = g * 16 + lr + ((lg >= 2) ? 8 : 0);
                    int col = t * 16 + ((lg & 1) ? 8 : 0);
                    ldm4(kb, skb + (uint32_t)(row * ASTR + col) * 2);
                    mma16816(s[2 * g], qf[t], kb);
                    mma16816(s[2 * g + 1], qf[t], kb + 2);
                }
            }
            const float sc = 0.125f;
#pragma unroll
            for (int n = 0; n < 8; n++)
#pragma unroll
                for (int u = 0; u < 4; u++) s[n][u] *= sc;
            if (kt * 64 + 63 > r0) {
                int cbase = kt * 64 + 2 * (lane & 3);
#pragma unroll
                for (int n = 0; n < 8; n++) {
                    int c0 = cbase + n * 8;
                    if (c0 > r0)         s[n][0] = -INFINITY;
                    if (c0 + 1 > r0)     s[n][1] = -INFINITY;
                    if (c0 > r0 + 8)     s[n][2] = -INFINITY;
                    if (c0 + 1 > r0 + 8) s[n][3] = -INFINITY;
                }
            }
            float mx0 = -INFINITY, mx1 = -INFINITY;
#pragma unroll
            for (int n = 0; n < 8; n++) {
                mx0 = fmaxf(mx0, fmaxf(s[n][0], s[n][1]));
                mx1 = fmaxf(mx1, fmaxf(s[n][2], s[n][3]));
            }
            mx0 = fmaxf(mx0, __shfl_xor_sync(0xFFFFFFFFu, mx0, 1));
            mx0 = fmaxf(mx0, __shfl_xor_sync(0xFFFFFFFFu, mx0, 2));
            mx1 = fmaxf(mx1, __shfl_xor_sync(0xFFFFFFFFu, mx1, 1));
            mx1 = fmaxf(mx1, __shfl_xor_sync(0xFFFFFFFFu, mx1, 2));
            float mn0 = fmaxf(mrow0, mx0), mn1 = fmaxf(mrow1, mx1);
            float al0 = __expf(mrow0 - mn0), al1 = __expf(mrow1 - mn1);
            mrow0 = mn0; mrow1 = mn1;
            float sum0 = 0.f, sum1 = 0.f;
#pragma unroll
            for (int n = 0; n < 8; n++) {
                s[n][0] = __expf(s[n][0] - mn0);
                s[n][1] = __expf(s[n][1] - mn0);
                s[n][2] = __expf(s[n][2] - mn1);
                s[n][3] = __expf(s[n][3] - mn1);
                sum0 += s[n][0] + s[n][1];
                sum1 += s[n][2] + s[n][3];
            }
            sum0 += __shfl_xor_sync(0xFFFFFFFFu, sum0, 1);
            sum0 += __shfl_xor_sync(0xFFFFFFFFu, sum0, 2);
            sum1 += __shfl_xor_sync(0xFFFFFFFFu, sum1, 1);
            sum1 += __shfl_xor_sync(0xFFFFFFFFu, sum1, 2);
            lrow0 = lrow0 * al0 + sum0;
            lrow1 = lrow1 * al1 + sum1;
#pragma unroll
            for (int n = 0; n < 8; n++) {
                o[n][0] *= al0; o[n][1] *= al0;
                o[n][2] *= al1; o[n][3] *= al1;
            }
            uint32_t pf[4][4];
#pragma unroll
            for (int t = 0; t < 4; t++) {
                pf[t][0] = pack_h2(s[2 * t][0], s[2 * t][1]);
                pf[t][1] = pack_h2(s[2 * t][2], s[2 * t][3]);
                pf[t][2] = pack_h2(s[2 * t + 1][0], s[2 * t + 1][1]);
                pf[t][3] = pack_h2(s[2 * t + 1][2], s[2 * t + 1][3]);
            }
#pragma unroll
            for (int t = 0; t < 4; t++) {
#pragma unroll
                for (int g = 0; g < 4; g++) {
                    uint32_t vb[4];
                    int row = t * 16 + lr + ((lg & 1) ? 8 : 0);
                    int col = g * 16 + ((lg >= 2) ? 8 : 0);
                    ldm4t(vb, svb + (uint32_t)(row * ASTR + col) * 2);
                    mma16816(o[2 * g], pf[t], vb);
                    mma16816(o[2 * g + 1], pf[t], vb + 2);
                }
            }
        }
        __syncthreads();
    }

    float inv0 = 1.f / lrow0, inv1 = 1.f / lrow1;
    size_t gr0 = (size_t)(b * L_ + r0);
    size_t gr1 = gr0 + 8;
    int col = h * 64 + 2 * (lane & 3);
#pragma unroll
    for (int n = 0; n < 8; n++) {
        int c = col + n * 8;
        float v0 = o[n][0] * inv0, v1 = o[n][1] * inv0;
        float v2 = o[n][2] * inv1, v3 = o[n][3] * inv1;
        __half h0 = __float2half(v0), h1 = __float2half(v1);
        __half h2 = __float2half(v2), h3 = __float2half(v3);
        *(__half2*)(oh + gr0 * D_ + c) = __halves2half2(h0, h1);
        *(__half2*)(ol + gr0 * D_ + c) =
            __halves2half2(__float2half(v0 - __half2float(h0)),
                           __float2half(v1 - __half2float(h1)));
        *(__half2*)(oh + gr1 * D_ + c) = __halves2half2(h2, h3);
        *(__half2*)(ol + gr1 * D_ + c) =
            __halves2half2(__float2half(v2 - __half2float(h2)),
                           __float2half(v3 - __half2float(h3)));
    }
}

// ======================= embedding / layernorm(+split) =======================
__global__ void embed_kernel(const int* __restrict__ x,
                             const float* __restrict__ tok,
                             const float* __restrict__ pos) {
    int i = blockIdx.x;
    int l = i & (L_ - 1);
    int idx = x[i];
    const float4* ts = (const float4*)(tok + (size_t)idx * D_);
    const float4* ps = (const float4*)(pos + (size_t)l * D_);
    float4* hp = (float4*)(g_h + (size_t)i * D_);
    for (int d = threadIdx.x; d < D_ / 4; d += blockDim.x) {
        float4 a = ts[d], b = ps[d];
        hp[d] = make_float4(a.x + b.x, a.y + b.y, a.z + b.z, a.w + b.w);
    }
}

__global__ __launch_bounds__(256) void ln_split_kernel(const float* __restrict__ x,
                                                       const float* __restrict__ g,
                                                       const float* __restrict__ bta,
                                                       __half* __restrict__ xh,
                                                       __half* __restrict__ xl) {
    int row = blockIdx.x, t = threadIdx.x;
    float2 v = ((const float2*)(x + (size_t)row * D_))[t];
    __shared__ float rs[256], rq[256];
    rs[t] = v.x + v.y;
    rq[t] = v.x * v.x + v.y * v.y;
    __syncthreads();
    for (int s = 128; s; s >>= 1) {
        if (t < s) { rs[t] += rs[t + s]; rq[t] += rq[t + s]; }
        __syncthreads();
    }
    float mu  = rs[0] * (1.0f / D_);
    float var = rq[0] * (1.0f / D_) - mu * mu;
    float inv = rsqrtf(var + 1e-5f);
    float2 gv = ((const float2*)g)[t];
    float2 bv = ((const float2*)bta)[t];
    float o0 = (v.x - mu) * inv * gv.x + bv.x;
    float o1 = (v.y - mu) * inv * gv.y + bv.y;
    __half h0 = __float2half(o0), h1 = __float2half(o1);
    ((__half2*)(xh + (size_t)row * D_))[t] = __halves2half2(h0, h1);
    ((__half2*)(xl + (size_t)row * D_))[t] =
        __halves2half2(__float2half(o0 - __half2float(h0)),
                       __float2half(o1 - __half2float(h1)));
}

// ======================= host orchestration ==================================
static inline void gemm_tc(int M, int N, int K,
                           const __half* ah, const __half* al,
                           const __half* bh,
                           const float* bias, const float* resid, float* C,
                           __half* H, __half* Hl, int act, int npass, int mode) {
    gemm_hmma_kernel<<<dim3(N / 128, M / 128), 256, GSMEM>>>(
        M, N, K, ah, al, bh, bias, resid, C, H, Hl, act, npass, mode);
}

extern "C" void kernel_launch(void* const* d_in, const int* in_sizes, int n_in,
                              void* d_out, int out_size) {
    const int*   x     = (const int*)d_in[0];
    const float* tok   = (const float*)d_in[1];
    const float* pos   = (const float*)d_in[2];
    const float* ln1g  = (const float*)d_in[3];
    const float* ln1b  = (const float*)d_in[4];
    const float* qkvw  = (const float*)d_in[5];
    const float* qkvb  = (const float*)d_in[6];
    const float* outw  = (const float*)d_in[7];
    const float* outb  = (const float*)d_in[8];
    const float* ln2g  = (const float*)d_in[9];
    const float* ln2b  = (const float*)d_in[10];
    const float* w1    = (const float*)d_in[11];
    const float* b1    = (const float*)d_in[12];
    const float* w2    = (const float*)d_in[13];
    const float* b2    = (const float*)d_in[14];
    const float* lnfg  = (const float*)d_in[15];
    const float* lnfb  = (const float*)d_in[16];
    const float* headw = (const float*)d_in[17];
    float* out = (float*)d_out;

    cudaFuncSetAttribute(gemm_hmma_kernel,
                         cudaFuncAttributeMaxDynamicSharedMemorySize, GSMEM);
    cudaFuncSetAttribute(gemm_head_kernel,
                         cudaFuncAttributeMaxDynamicSharedMemorySize, HSMEM);
    cudaFuncSetAttribute(attn_kernel,
                         cudaFuncAttributeMaxDynamicSharedMemorySize, ATT_SMEM);

    float* ph;
    cudaGetSymbolAddress((void**)&ph, g_h);
    __half *wqh, *woh, *w1h, *w2h, *hdh;
    __half *q16, *xh, *xl, *yh, *yl;
    cudaGetSymbolAddress((void**)&wqh, g_wq_h);
    cudaGetSymbolAddress((void**)&woh, g_wo_h);
    cudaGetSymbolAddress((void**)&w1h, g_w1_h);
    cudaGetSymbolAddress((void**)&w2h, g_w2_h);
    cudaGetSymbolAddress((void**)&hdh, g_hd_h);
    cudaGetSymbolAddress((void**)&q16, g_q16);
    cudaGetSymbolAddress((void**)&xh, g_xh);    cudaGetSymbolAddress((void**)&xl, g_xl);
    cudaGetSymbolAddress((void**)&yh, g_yh);    cudaGetSymbolAddress((void**)&yl, g_yl);

    // Launch order arranged so ncu (-s 5 -c 1) captures the QKV GEMM.
    // 1: wsplit qkv  2: embed  3: ln  4: wsplit wo  5: wsplit w1  6: gemm QKV
    wsplit_kernel<<<dim3(D3_ / 32, D_ / 32, NL_), 256>>>(
        qkvw, D_, D3_, wqh, (size_t)D_ * D3_, (size_t)D3_ * D_);
    embed_kernel<<<BL_, 128>>>(x, tok, pos);
    ln_split_kernel<<<BL_, 256>>>(ph, ln1g, ln1b, xh, xl);
    wsplit_kernel<<<dim3(D_ / 32, D_ / 32, NL_), 256>>>(
        outw, D_, D_, woh, (size_t)D_ * D_, (size_t)D_ * D_);
    wsplit_kernel<<<dim3(DM_ / 32, D_ / 32, NL_), 256>>>(
        w1, D_, DM_, w1h, (size_t)D_ * DM_, (size_t)DM_ * D_);

    for (int i = 0; i < NL_; i++) {
        if (i > 0)
            ln_split_kernel<<<BL_, 256>>>(ph, ln1g + i * D_, ln1b + i * D_, xh, xl);
        // QKV -> fp16 (mode 1), 2-pass
        gemm_tc(BL_, D3_, D_, xh, xl,
                wqh + (size_t)i * D3_ * D_,
                qkvb + (size_t)i * D3_, nullptr, nullptr, q16, nullptr, 0, 2, 1);
        // fused flash attention -> split O
        attn_kernel<<<dim3(L_ / 128, B_ * NH_), 256, ATT_SMEM>>>(q16, xh, xl);
        // proj + residual, 2-pass
        gemm_tc(BL_, D_, D_, xh, xl,
                woh + (size_t)i * D_ * D_,
                outb + (size_t)i * D_, ph, ph, nullptr, nullptr, 0, 2, 0);
        ln_split_kernel<<<BL_, 256>>>(ph, ln2g + i * D_, ln2b + i * D_, xh, xl);
        // MLP up + GELU -> split, 2-pass
        gemm_tc(BL_, DM_, D_, xh, xl,
                w1h + (size_t)i * DM_ * D_,
                b1 + (size_t)i * DM_, nullptr, nullptr, yh, yl, 1, 2, 2);
        if (i == 0)  // w2 transpose deferred until first use (keeps QKV at launch #6)
            wsplit_kernel<<<dim3(D_ / 32, DM_ / 32, NL_), 256>>>(
                w2, DM_, D_, w2h, (size_t)DM_ * D_, (size_t)D_ * DM_);
        // MLP down + residual, 2-pass
        gemm_tc(BL_, D_, DM_, yh, yl,
                w2h + (size_t)i * D_ * DM_,
                b2 + (size_t)i * D_, ph, ph, nullptr, nullptr, 0, 2, 0);
    }

    wsplit_kernel<<<dim3(V_ / 32, D_ / 32, 1), 256>>>(headw, D_, V_, hdh, 0, 0);
    ln_split_kernel<<<BL_, 256>>>(ph, lnfg, lnfb, xh, xl);
    // vocab head: fp16-acc HMMA with 64-K segment promotion to fp32
    gemm_head_kernel<<<dim3(V_ / 128, BL_ / 128), 256, HSMEM>>>(
        BL_, V_, D_, xh, hdh, out);
}